// round 4
// baseline (speedup 1.0000x reference)
#include <cuda_runtime.h>

// PINN via tabulated jets: the input is scalar x in [0,1), so all 8 outputs
// are fixed smooth 1-D functions of x. Kernel A computes an order-6 jet
// (fp64) at 4097 grid nodes (spacing 2^-12); kernel B does 2nd-order Taylor
// interpolation from the nearest node for 2M points.
// Outputs per point: [u, u_x, u_xx, w, w_x, w_xx, w_xxx, w_xxxx].

#define KNODES 4097            // nodes at j * 2^-12, j = 0..4096
#define HINV   4096.0f
#define HF     0.000244140625f // 2^-12, exact in fp32/fp64

// per node: a=(u0,u1,u2,u3) b=(u4,w0,w1,w2) c=(w3,w4,w5,w6)
__device__ float4 g_table[KNODES * 3];

// ---------------- Kernel A: exact order-6 jets at nodes (fp64) ----------------

__global__ void pinn_build_table(const float* __restrict__ gW0, const float* __restrict__ gb0,
                                 const float* __restrict__ gW1, const float* __restrict__ gb1,
                                 const float* __restrict__ gW2, const float* __restrict__ gb2)
{
    int j = blockIdx.x * blockDim.x + threadIdx.x;
    if (j >= KNODES) return;

    const double x0 = (double)j * (double)HF;

    // Layer 0: z = w*x + b; z1 = w, z>=2 = 0 -> h_m = d_m(t) * w^m
    double h[7][8];
    for (int k = 0; k < 8; ++k) {
        double w = (double)gW0[k];
        double z = w * x0 + (double)gb0[k];
        double t = tanh(z);
        double t2 = t * t;
        double s  = 1.0 - t2;
        double d2 = -2.0 * t * s;
        double d3 = s * (6.0 * t2 - 2.0);
        double d4 = t * s * (16.0 - 24.0 * t2);
        double d5 = s * (16.0 + t2 * (-120.0 + 120.0 * t2));
        double d6 = s * t * (-272.0 + t2 * (960.0 - 720.0 * t2));
        double w2 = w * w, w3 = w2 * w;
        h[0][k] = t;
        h[1][k] = s  * w;
        h[2][k] = d2 * w2;
        h[3][k] = d3 * w3;
        h[4][k] = d4 * w2 * w2;
        h[5][k] = d5 * w2 * w3;
        h[6][k] = d6 * w3 * w3;
    }

    double u[5]; double wv[7];
    u[0] = (double)gb2[0]; u[1] = u[2] = u[3] = u[4] = 0.0;
    wv[0] = (double)gb2[1];
    for (int m = 1; m < 7; ++m) wv[m] = 0.0;

    // Layer 1 (8x8) jets + tanh composition (Faa di Bruno to order 6),
    // output layer fused.
    for (int jn = 0; jn < 8; ++jn) {
        double z[7];
        z[0] = (double)gb1[jn];
        for (int m = 1; m < 7; ++m) z[m] = 0.0;
        for (int k = 0; k < 8; ++k) {
            double w = (double)gW1[jn * 8 + k];
            for (int m = 0; m < 7; ++m) z[m] += w * h[m][k];
        }
        double t = tanh(z[0]);
        double t2 = t * t;
        double s  = 1.0 - t2;
        double d1 = s;
        double d2 = -2.0 * t * s;
        double d3 = s * (6.0 * t2 - 2.0);
        double d4 = t * s * (16.0 - 24.0 * t2);
        double d5 = s * (16.0 + t2 * (-120.0 + 120.0 * t2));
        double d6 = s * t * (-272.0 + t2 * (960.0 - 720.0 * t2));

        double z1 = z[1], z2 = z[2], z3 = z[3], z4 = z[4], z5 = z[5], z6 = z[6];
        double z1_2 = z1 * z1, z1_3 = z1_2 * z1, z1_4 = z1_2 * z1_2;
        double g[7];
        g[0] = t;
        g[1] = d1 * z1;
        g[2] = d1 * z2 + d2 * z1_2;
        g[3] = d1 * z3 + 3.0 * d2 * z1 * z2 + d3 * z1_3;
        g[4] = d1 * z4 + d2 * (4.0 * z1 * z3 + 3.0 * z2 * z2)
             + 6.0 * d3 * z1_2 * z2 + d4 * z1_4;
        g[5] = d1 * z5 + d2 * (5.0 * z1 * z4 + 10.0 * z2 * z3)
             + d3 * (10.0 * z1_2 * z3 + 15.0 * z1 * z2 * z2)
             + 10.0 * d4 * z1_3 * z2 + d5 * z1_4 * z1;
        g[6] = d1 * z6 + d2 * (6.0 * z1 * z5 + 15.0 * z2 * z4 + 10.0 * z3 * z3)
             + d3 * (15.0 * z1_2 * z4 + 60.0 * z1 * z2 * z3 + 15.0 * z2 * z2 * z2)
             + d4 * (20.0 * z1_3 * z3 + 45.0 * z1_2 * z2 * z2)
             + 15.0 * d5 * z1_4 * z2 + d6 * z1_4 * z1_2;

        double wu = (double)gW2[jn];
        double ww = (double)gW2[8 + jn];
        for (int m = 0; m < 5; ++m) u[m]  += wu * g[m];
        for (int m = 0; m < 7; ++m) wv[m] += ww * g[m];
    }

    float4* tb = &g_table[j * 3];
    tb[0] = make_float4((float)u[0],  (float)u[1],  (float)u[2],  (float)u[3]);
    tb[1] = make_float4((float)u[4],  (float)wv[0], (float)wv[1], (float)wv[2]);
    tb[2] = make_float4((float)wv[3], (float)wv[4], (float)wv[5], (float)wv[6]);
}

// ---------------- Kernel B: Taylor interpolation for all points ----------------

__global__ __launch_bounds__(256)
void pinn_interp(const float* __restrict__ x, float* __restrict__ out, int n)
{
    int i = blockIdx.x * blockDim.x + threadIdx.x;
    if (i >= n) return;

    float xv = x[i];
    float fj = rintf(xv * HINV);
    int j = (int)fj;
    float dx = fmaf(fj, -HF, xv);       // exact: fj*HF is a power-of-two product
    float t2 = 0.5f * dx * dx;

    const float4* tb = &g_table[j * 3];
    float4 a = __ldg(&tb[0]);
    float4 b = __ldg(&tb[1]);
    float4 c = __ldg(&tb[2]);

    float u    = fmaf(t2, a.z, fmaf(dx, a.y, a.x));
    float ux   = fmaf(t2, a.w, fmaf(dx, a.z, a.y));
    float uxx  = fmaf(t2, b.x, fmaf(dx, a.w, a.z));
    float w    = fmaf(t2, b.w, fmaf(dx, b.z, b.y));
    float wx   = fmaf(t2, c.x, fmaf(dx, b.w, b.z));
    float wxx  = fmaf(t2, c.y, fmaf(dx, c.x, b.w));
    float wxxx = fmaf(t2, c.z, fmaf(dx, c.y, c.x));
    float wxxxx= fmaf(t2, c.w, fmaf(dx, c.z, c.y));

    float4* op = reinterpret_cast<float4*>(out + (size_t)i * 8);
    op[0] = make_float4(u, ux, uxx, w);
    op[1] = make_float4(wx, wxx, wxxx, wxxxx);
}

extern "C" void kernel_launch(void* const* d_in, const int* in_sizes, int n_in,
                              void* d_out, int out_size)
{
    const float* x  = (const float*)d_in[0];
    const float* W0 = (const float*)d_in[1];
    const float* b0 = (const float*)d_in[2];
    const float* W1 = (const float*)d_in[3];
    const float* b1 = (const float*)d_in[4];
    const float* W2 = (const float*)d_in[5];
    const float* b2 = (const float*)d_in[6];
    float* out = (float*)d_out;

    int n = in_sizes[0];

    pinn_build_table<<<(KNODES + 255) / 256, 256>>>(W0, b0, W1, b1, W2, b2);
    pinn_interp<<<(n + 255) / 256, 256>>>(x, out, n);
}

// round 5
// speedup vs baseline: 5.0888x; 5.0888x over previous
#include <cuda_runtime.h>

// PINN via tabulated jets. Input is scalar x in [0,1): all 8 outputs are
// fixed smooth 1-D functions. Kernel A: order-6 jets (fp32, accurate tanhf)
// at 4097 nodes (h = 2^-12). Kernel B: persistent blocks stage the 192KB
// table in shared memory, then 2nd-order Taylor interpolation per point.
// Outputs per point: [u, u_x, u_xx, w, w_x, w_xx, w_xxx, w_xxxx].

#define KNODES 4097
#define HINV   4096.0f
#define HF     0.000244140625f   // 2^-12 exact

#define TBL_FLOATS (KNODES * 12) // 12 floats per node = 48B, 16B-aligned
__device__ float g_table[TBL_FLOATS];

// ---------------- Kernel A: order-6 jets at nodes (fp32, tanhf) ----------------

__global__ void pinn_build_table(const float* __restrict__ gW0, const float* __restrict__ gb0,
                                 const float* __restrict__ gW1, const float* __restrict__ gb1,
                                 const float* __restrict__ gW2, const float* __restrict__ gb2)
{
    int j = blockIdx.x * blockDim.x + threadIdx.x;
    if (j >= KNODES) return;

    const float x0 = (float)j * HF;

    // Layer 0: scalar input -> jet h_m = d_m(tanh) * w^m
    float h[7][8];
#pragma unroll
    for (int k = 0; k < 8; ++k) {
        float w = gW0[k];
        float z = fmaf(w, x0, gb0[k]);
        float t = tanhf(z);
        float t2 = t * t;
        float s  = 1.0f - t2;
        float d2 = -2.0f * t * s;
        float d3 = s * (6.0f * t2 - 2.0f);
        float d4 = t * s * (16.0f - 24.0f * t2);
        float d5 = s * (16.0f + t2 * (-120.0f + 120.0f * t2));
        float d6 = s * t * (-272.0f + t2 * (960.0f - 720.0f * t2));
        float w2 = w * w, w3 = w2 * w;
        h[0][k] = t;
        h[1][k] = s  * w;
        h[2][k] = d2 * w2;
        h[3][k] = d3 * w3;
        h[4][k] = d4 * w2 * w2;
        h[5][k] = d5 * w2 * w3;
        h[6][k] = d6 * w3 * w3;
    }

    float u[5]; float wv[7];
    u[0] = gb2[0]; u[1] = u[2] = u[3] = u[4] = 0.0f;
    wv[0] = gb2[1];
#pragma unroll
    for (int m = 1; m < 7; ++m) wv[m] = 0.0f;

    // Layer 1 (8x8) + tanh composition (Faa di Bruno to order 6), output fused
    for (int jn = 0; jn < 8; ++jn) {
        float z[7];
        z[0] = gb1[jn];
#pragma unroll
        for (int m = 1; m < 7; ++m) z[m] = 0.0f;
        for (int k = 0; k < 8; ++k) {
            float w = gW1[jn * 8 + k];
#pragma unroll
            for (int m = 0; m < 7; ++m) z[m] = fmaf(w, h[m][k], z[m]);
        }
        float t = tanhf(z[0]);
        float t2 = t * t;
        float s  = 1.0f - t2;
        float d1 = s;
        float d2 = -2.0f * t * s;
        float d3 = s * (6.0f * t2 - 2.0f);
        float d4 = t * s * (16.0f - 24.0f * t2);
        float d5 = s * (16.0f + t2 * (-120.0f + 120.0f * t2));
        float d6 = s * t * (-272.0f + t2 * (960.0f - 720.0f * t2));

        float z1 = z[1], z2 = z[2], z3 = z[3], z4 = z[4], z5 = z[5], z6 = z[6];
        float z1_2 = z1 * z1, z1_3 = z1_2 * z1, z1_4 = z1_2 * z1_2;
        float g[7];
        g[0] = t;
        g[1] = d1 * z1;
        g[2] = d1 * z2 + d2 * z1_2;
        g[3] = d1 * z3 + 3.0f * d2 * z1 * z2 + d3 * z1_3;
        g[4] = d1 * z4 + d2 * (4.0f * z1 * z3 + 3.0f * z2 * z2)
             + 6.0f * d3 * z1_2 * z2 + d4 * z1_4;
        g[5] = d1 * z5 + d2 * (5.0f * z1 * z4 + 10.0f * z2 * z3)
             + d3 * (10.0f * z1_2 * z3 + 15.0f * z1 * z2 * z2)
             + 10.0f * d4 * z1_3 * z2 + d5 * z1_4 * z1;
        g[6] = d1 * z6 + d2 * (6.0f * z1 * z5 + 15.0f * z2 * z4 + 10.0f * z3 * z3)
             + d3 * (15.0f * z1_2 * z4 + 60.0f * z1 * z2 * z3 + 15.0f * z2 * z2 * z2)
             + d4 * (20.0f * z1_3 * z3 + 45.0f * z1_2 * z2 * z2)
             + 15.0f * d5 * z1_4 * z2 + d6 * z1_4 * z1_2;

        float wu = gW2[jn];
        float ww = gW2[8 + jn];
#pragma unroll
        for (int m = 0; m < 5; ++m) u[m]  = fmaf(wu, g[m], u[m]);
#pragma unroll
        for (int m = 0; m < 7; ++m) wv[m] = fmaf(ww, g[m], wv[m]);
    }

    float4* tb = reinterpret_cast<float4*>(g_table) + j * 3;
    tb[0] = make_float4(u[0],  u[1],  u[2],  u[3]);
    tb[1] = make_float4(u[4],  wv[0], wv[1], wv[2]);
    tb[2] = make_float4(wv[3], wv[4], wv[5], wv[6]);
}

// ---------------- Kernel B: persistent, smem table, Taylor interp ----------------

#define INTERP_BLOCK 1024
#define INTERP_GRID  148

__global__ __launch_bounds__(INTERP_BLOCK, 1)
void pinn_interp(const float* __restrict__ x, float* __restrict__ out, int n)
{
    extern __shared__ float s_table[];

    // stage full table into shared (192.8 KB)
    for (int idx = threadIdx.x; idx < TBL_FLOATS; idx += INTERP_BLOCK)
        s_table[idx] = g_table[idx];
    __syncthreads();

    const float4* tbl4 = reinterpret_cast<const float4*>(s_table);

    for (int i = blockIdx.x * INTERP_BLOCK + threadIdx.x; i < n;
         i += INTERP_GRID * INTERP_BLOCK)
    {
        float xv = x[i];
        float fj = rintf(xv * HINV);
        int j = (int)fj;
        float dx = fmaf(fj, -HF, xv);
        float t2 = 0.5f * dx * dx;

        float4 a = tbl4[j * 3 + 0];
        float4 b = tbl4[j * 3 + 1];
        float4 c = tbl4[j * 3 + 2];

        float u     = fmaf(t2, a.z, fmaf(dx, a.y, a.x));
        float ux    = fmaf(t2, a.w, fmaf(dx, a.z, a.y));
        float uxx   = fmaf(t2, b.x, fmaf(dx, a.w, a.z));
        float w     = fmaf(t2, b.w, fmaf(dx, b.z, b.y));
        float wx    = fmaf(t2, c.x, fmaf(dx, b.w, b.z));
        float wxx   = fmaf(t2, c.y, fmaf(dx, c.x, b.w));
        float wxxx  = fmaf(t2, c.z, fmaf(dx, c.y, c.x));
        float wxxxx = fmaf(t2, c.w, fmaf(dx, c.z, c.y));

        float4* op = reinterpret_cast<float4*>(out + (size_t)i * 8);
        op[0] = make_float4(u, ux, uxx, w);
        op[1] = make_float4(wx, wxx, wxxx, wxxxx);
    }
}

extern "C" void kernel_launch(void* const* d_in, const int* in_sizes, int n_in,
                              void* d_out, int out_size)
{
    const float* x  = (const float*)d_in[0];
    const float* W0 = (const float*)d_in[1];
    const float* b0 = (const float*)d_in[2];
    const float* W1 = (const float*)d_in[3];
    const float* b1 = (const float*)d_in[4];
    const float* W2 = (const float*)d_in[5];
    const float* b2 = (const float*)d_in[6];
    float* out = (float*)d_out;

    int n = in_sizes[0];
    const int smem_bytes = TBL_FLOATS * (int)sizeof(float);  // ~192.8 KB

    cudaFuncSetAttribute(pinn_interp,
                         cudaFuncAttributeMaxDynamicSharedMemorySize, smem_bytes);

    pinn_build_table<<<(KNODES + 255) / 256, 256>>>(W0, b0, W1, b1, W2, b2);
    pinn_interp<<<INTERP_GRID, INTERP_BLOCK, smem_bytes>>>(x, out, n);
}